// round 11
// baseline (speedup 1.0000x reference)
#include <cuda_runtime.h>
#include <cuda_bf16.h>
#include <cstdint>

// Problem constants
#define BATCH 8
#define NQ    2048
#define NS    4096
#define DIM   512

// Tiling: persistent grid of 148 blocks, 512 threads = two independent
// 256-thread pipelines (own named barrier, own B ring). Work units are
// s-tiles: u = qid*32 + st, qid = b*16 + qt (4096 units total). Each block
// owns a contiguous static slice; A tile reloaded at qid boundaries.
#define BM 128
#define BN 128
#define BK 64
#define NBUF 3
#define NTHREADS 512
#define GRID 148
#define NUNITS (BATCH * 16 * 32)     // 4096

#define A_BYTES    (BM * DIM * 2)              // 131072 = 8 chunks of 16KB
#define BBUF_BYTES (BN * BK * 2)               // 16384
#define RM_OFF     (A_BYTES + 2 * NBUF * BBUF_BYTES)   // 229376
#define SMEM_TOTAL (RM_OFF + BM * 4)                   // 229888

// Device scratch
__device__ __nv_bfloat16 g_qn[(size_t)BATCH * NQ * DIM];
__device__ __nv_bfloat16 g_sn[(size_t)BATCH * NS * DIM];
__device__ unsigned      g_rmax[(size_t)BATCH * NQ];   // monotone fp keys
__device__ unsigned      g_done;                       // persistent done counter

// ---------------------------------------------------------------------------
// helpers
// ---------------------------------------------------------------------------
__device__ __forceinline__ uint32_t swz(uint32_t x) {   // SW128: bits[6:4] ^= bits[9:7]
    return x ^ ((x >> 3) & 0x70);
}
__device__ __forceinline__ void cp_async16(uint32_t saddr, const void* gptr) {
    asm volatile("cp.async.cg.shared.global [%0], [%1], 16;\n" :: "r"(saddr), "l"(gptr));
}
__device__ __forceinline__ void cp_commit() {
    asm volatile("cp.async.commit_group;\n" ::: "memory");
}
template <int N>
__device__ __forceinline__ void cp_wait() {
    asm volatile("cp.async.wait_group %0;\n" :: "n"(N) : "memory");
}
__device__ __forceinline__ void bar_g(int id) {
    asm volatile("bar.sync %0, 256;" :: "r"(id) : "memory");
}
__device__ __forceinline__ unsigned fkey(float f) {
    unsigned u = __float_as_uint(f);
    return (u & 0x80000000u) ? ~u : (u | 0x80000000u);
}
__device__ __forceinline__ float funkey(unsigned k) {
    unsigned u = (k & 0x80000000u) ? (k ^ 0x80000000u) : ~k;
    return __uint_as_float(u);
}

// ---------------------------------------------------------------------------
// Normalize: one warp per row of 512 fp32 -> bf16. Also inits g_rmax keys.
// ---------------------------------------------------------------------------
__device__ __forceinline__ void normalize_row(const float* __restrict__ rinF,
                                              __nv_bfloat16* __restrict__ orow, int lane)
{
    const float4* rin = reinterpret_cast<const float4*>(rinF);
    float4 v[4];
    float s = 0.f;
#pragma unroll
    for (int j = 0; j < 4; j++) {
        v[j] = rin[j * 32 + lane];
        s += v[j].x * v[j].x + v[j].y * v[j].y + v[j].z * v[j].z + v[j].w * v[j].w;
    }
#pragma unroll
    for (int o = 16; o > 0; o >>= 1) s += __shfl_xor_sync(0xFFFFFFFFu, s, o);
    float inv = 1.0f / fmaxf(sqrtf(s), 1e-12f);
#pragma unroll
    for (int j = 0; j < 4; j++) {
        __nv_bfloat162 h0 = __floats2bfloat162_rn(v[j].x * inv, v[j].y * inv);
        __nv_bfloat162 h1 = __floats2bfloat162_rn(v[j].z * inv, v[j].w * inv);
        uint2 pk;
        pk.x = *reinterpret_cast<unsigned*>(&h0);
        pk.y = *reinterpret_cast<unsigned*>(&h1);
        *reinterpret_cast<uint2*>(orow + (size_t)(j * 32 + lane) * 4) = pk;
    }
}

__global__ void normalize_all_kernel(const float* __restrict__ q,
                                     const float* __restrict__ s)
{
    int gtid = blockIdx.x * blockDim.x + threadIdx.x;
    if (gtid < BATCH * NQ) g_rmax[gtid] = 0u;   // key 0 == -inf-ish
    int row = blockIdx.x * (blockDim.x >> 5) + (threadIdx.x >> 5);
    int lane = threadIdx.x & 31;
    const int nq = BATCH * NQ;
    const int ntot = nq + BATCH * NS;
    if (row >= ntot) return;
    if (row < nq)
        normalize_row(q + (size_t)row * DIM, g_qn + (size_t)row * DIM, lane);
    else {
        int r = row - nq;
        normalize_row(s + (size_t)r * DIM, g_sn + (size_t)r * DIM, lane);
    }
}

// ---------------------------------------------------------------------------
// B chunk fill: s-tile st (within batch), k-cols [kc*64,+64), ring slot.
// 1024 x 16B segments, 4 per group-thread.
// ---------------------------------------------------------------------------
__device__ __forceinline__ void fill_b_chunk(uint32_t smem_u32,
                                             const __nv_bfloat16* __restrict__ gB,
                                             int st, int kc, int slot,
                                             int gid, int gtid)
{
    const uint32_t bb = A_BYTES + (uint32_t)(gid * NBUF + slot) * BBUF_BYTES;
#pragma unroll
    for (int i = 0; i < 4; i++) {
        int idx = gtid + i * 256;        // 0..1023
        int r = idx >> 3;                // 8 segs per 128B row
        int s8 = idx & 7;
        const void* src = gB + (size_t)(st * BN + r) * DIM + kc * BK + s8 * 8;
        cp_async16(smem_u32 + bb + swz((uint32_t)(r * 128 + s8 * 16)), src);
    }
    cp_commit();
}

// ---------------------------------------------------------------------------
// Persistent GEMM-max. 148 blocks x 512 threads (2 groups). Static unit
// slices; A resident per qid; global atomicMax epilogue; last block reduces.
// ---------------------------------------------------------------------------
__global__ __launch_bounds__(NTHREADS, 1) void gemm_max_kernel(float* __restrict__ out)
{
    extern __shared__ char smem[];
    unsigned* rowmaxU = reinterpret_cast<unsigned*>(smem + RM_OFF);
    __shared__ float red[NTHREADS / 32];
    __shared__ unsigned s_last;
    const uint32_t smem_u32 = (uint32_t)__cvta_generic_to_shared(smem);

    const int bid = blockIdx.x;
    const int tid = threadIdx.x;
    const int lane = tid & 31;
    const int wid  = tid >> 5;
    const int gid  = wid >> 3;           // warp-group 0 / 1
    const int gtid = tid & 255;
    const int gwid = wid & 7;
    const int wm = (gwid >> 2) * 64;
    const int wn = (gwid & 3) * 32;

    const int u0 = (bid * NUNITS) / GRID;
    const int u1 = ((bid + 1) * NUNITS) / GRID;

    float C[4][4][4];
#pragma unroll
    for (int mi = 0; mi < 4; mi++)
#pragma unroll
        for (int ni = 0; ni < 4; ni++)
#pragma unroll
            for (int e = 0; e < 4; e++) C[mi][ni][e] = 0.f;

    int pq = -1;   // previous qid (for flush)
    const int qidA = u0 >> 5;
    const int qidB = (u1 - 1) >> 5;

    for (int qid = qidA; qid <= qidB; qid++) {
        const int a = max(u0, qid << 5);
        const int e = min(u1, (qid << 5) + 32);

        // --- boundary: drain fills, rendezvous, flush previous qid ---
        cp_wait<0>();
        __syncthreads();
        if (tid < BM) {
            if (pq >= 0) atomicMax(&g_rmax[pq * BM + tid], rowmaxU[tid]);
            rowmaxU[tid] = 0u;
        }

        // --- A tile for qid: rows qid*128..+128 of g_qn ---
        const __nv_bfloat16* gA = g_qn + (size_t)qid * BM * DIM;
#pragma unroll
        for (int i = 0; i < 16; i++) {
            int idx = tid + i * NTHREADS;    // 0..8191 16B segs
            int r = idx >> 6;
            int rest = idx & 63;
            int ch = rest >> 3;
            int s8 = rest & 7;
            const void* src = gA + (size_t)r * DIM + ch * 64 + s8 * 8;
            cp_async16(smem_u32 + ch * 16384 + swz((uint32_t)(r * 128 + s8 * 16)), src);
        }
        cp_commit();

        // --- group sub-range of units in this qid ---
        const int n = e - a;
        const int half = (n + 1) >> 1;
        const int ga = gid ? a + half : a;
        const int ge = gid ? e : a + half;
        const int nch = (ge - ga) * 8;
        const int b = qid >> 4;
        const __nv_bfloat16* gB = g_sn + (size_t)b * NS * DIM;

        if (nch > 0) {
            fill_b_chunk(smem_u32, gB, ga & 31, 0, 0, gid, gtid);
            fill_b_chunk(smem_u32, gB, (nch > 8 ? (ga + 0) : ga) & 31, 1, 1, gid, gtid);
            cp_wait<2>();                // A (oldest) complete
        } else {
            cp_wait<0>();
        }
        __syncthreads();                 // A + rowmax reset visible to all

        float rmax[4][2];
#pragma unroll
        for (int t = 0; t < 4; t++) { rmax[t][0] = -1e30f; rmax[t][1] = -1e30f; }

        for (int j = 0; j < nch; j++) {
            if (j + 1 < nch) cp_wait<1>(); else cp_wait<0>();
            bar_g(1 + gid);
            if (j + 2 < nch) {
                int ju = j + 2;
                fill_b_chunk(smem_u32, gB, (ga + (ju >> 3)) & 31, ju & 7,
                             ju % NBUF, gid, gtid);
            }

            const int kc = j & 7;        // A chunk index for this k-range
            const uint32_t bb = A_BYTES
                              + (uint32_t)(gid * NBUF + (j % NBUF)) * BBUF_BYTES;

#pragma unroll
            for (int ksp = 0; ksp < 2; ksp++) {
                unsigned bfr[4][4];
                {
                    const uint32_t kb = (uint32_t)(ksp * 64
                                      + ((lane >> 3) & 1) * 16 + (lane >> 4) * 32);
#pragma unroll
                    for (int ni = 0; ni < 4; ni++) {
                        int nn = wn + ni * 8 + (lane & 7);
                        uint32_t addr = smem_u32 + bb + swz((uint32_t)(nn * 128) + kb);
                        asm volatile("ldmatrix.sync.aligned.m8n8.x4.shared.b16 {%0,%1,%2,%3}, [%4];"
                                     : "=r"(bfr[ni][0]), "=r"(bfr[ni][1]),
                                       "=r"(bfr[ni][2]), "=r"(bfr[ni][3])
                                     : "r"(addr));
                    }
                }
#pragma unroll
                for (int h = 0; h < 2; h++) {
                    const int ks = ksp * 2 + h;
                    const uint32_t kb = (uint32_t)(ks * 32 + (lane >> 4) * 16);
                    unsigned af[4][4];
#pragma unroll
                    for (int mi = 0; mi < 4; mi++) {
                        int r0 = wm + mi * 16 + (lane & 15);
                        uint32_t addr = smem_u32 + kc * 16384
                                      + swz((uint32_t)(r0 * 128) + kb);
                        asm volatile("ldmatrix.sync.aligned.m8n8.x4.shared.b16 {%0,%1,%2,%3}, [%4];"
                                     : "=r"(af[mi][0]), "=r"(af[mi][1]),
                                       "=r"(af[mi][2]), "=r"(af[mi][3])
                                     : "r"(addr));
                    }
#pragma unroll
                    for (int mi = 0; mi < 4; mi++)
#pragma unroll
                        for (int ni = 0; ni < 4; ni++) {
                            asm volatile(
                                "mma.sync.aligned.m16n8k16.row.col.f32.bf16.bf16.f32 "
                                "{%0,%1,%2,%3}, {%4,%5,%6,%7}, {%8,%9}, {%0,%1,%2,%3};"
                                : "+f"(C[mi][ni][0]), "+f"(C[mi][ni][1]),
                                  "+f"(C[mi][ni][2]), "+f"(C[mi][ni][3])
                                : "r"(af[mi][0]), "r"(af[mi][1]),
                                  "r"(af[mi][2]), "r"(af[mi][3]),
                                  "r"(bfr[ni][2 * h]), "r"(bfr[ni][2 * h + 1]));
                        }
                }
            }

            if ((j & 7) == 7) {          // end of s-tile: fold max, reset C
#pragma unroll
                for (int mi = 0; mi < 4; mi++) {
                    float m0 = rmax[mi][0], m1 = rmax[mi][1];
#pragma unroll
                    for (int ni = 0; ni < 4; ni++) {
                        m0 = fmaxf(m0, fmaxf(C[mi][ni][0], C[mi][ni][1]));
                        m1 = fmaxf(m1, fmaxf(C[mi][ni][2], C[mi][ni][3]));
                        C[mi][ni][0] = 0.f; C[mi][ni][1] = 0.f;
                        C[mi][ni][2] = 0.f; C[mi][ni][3] = 0.f;
                    }
                    rmax[mi][0] = m0; rmax[mi][1] = m1;
                }
            }
        }

        // group epilogue for this qid: fold into smem rowmax
#pragma unroll
        for (int t = 0; t < 4; t++) {
#pragma unroll
            for (int g = 0; g < 2; g++) {
                int row = wm + t * 16 + (lane >> 2) + g * 8;
                atomicMax(&rowmaxU[row], fkey(rmax[t][g]));
            }
        }
        pq = qid;
    }

    // final flush of last qid
    cp_wait<0>();
    __syncthreads();
    if (tid < BM && pq >= 0) atomicMax(&g_rmax[pq * BM + tid], rowmaxU[tid]);
    __threadfence();
    __syncthreads();

    // done counter; last block computes out[]
    if (tid == 0) s_last = (atomicAdd(&g_done, 1u) == GRID - 1) ? 1u : 0u;
    __syncthreads();
    if (s_last) {
        __threadfence();
        for (int bb2 = 0; bb2 < BATCH; bb2++) {
            float s = 0.f;
            for (int i = tid; i < NQ; i += NTHREADS)
                s += 1.0f - funkey(g_rmax[(size_t)bb2 * NQ + i]);
#pragma unroll
            for (int o = 16; o > 0; o >>= 1) s += __shfl_xor_sync(0xFFFFFFFFu, s, o);
            if (lane == 0) red[wid] = s;
            __syncthreads();
            if (wid == 0) {
                float t2 = (lane < NTHREADS / 32) ? red[lane] : 0.f;
#pragma unroll
                for (int o = 8; o > 0; o >>= 1)
                    t2 += __shfl_xor_sync(0xFFFFFFFFu, t2, o);
                if (lane == 0) out[bb2] = t2 * (1.0f / NQ);
            }
            __syncthreads();
        }
        if (tid == 0) g_done = 0u;       // reset for next graph replay
    }
}

// ---------------------------------------------------------------------------
extern "C" void kernel_launch(void* const* d_in, const int* in_sizes, int n_in,
                              void* d_out, int out_size)
{
    const float* q = (const float*)d_in[0];
    const float* s = (const float*)d_in[1];
    float* out = (float*)d_out;

    cudaFuncSetAttribute(gemm_max_kernel,
                         cudaFuncAttributeMaxDynamicSharedMemorySize, SMEM_TOTAL);

    const int nrows = BATCH * (NQ + NS);
    normalize_all_kernel<<<(nrows + 7) / 8, 256>>>(q, s);
    gemm_max_kernel<<<GRID, NTHREADS, SMEM_TOTAL>>>(out);
}